// round 1
// baseline (speedup 1.0000x reference)
#include <cuda_runtime.h>
#include <cuda_bf16.h>

#define N_NODES 100000
#define N_EDGES 1600000
#define D 64
#define NEG_SLOPE 0.1f

// Scratch (allocation-free rule: __device__ globals)
__device__ float    g_e[N_EDGES];    // logits, then exp(e - max)
__device__ unsigned g_m[N_NODES];    // ordered-uint encoded segment max
__device__ float    g_den[N_NODES];  // softmax denominator

// Ordered-uint encoding so unsigned atomicMax == float max.
// encode: non-negative -> set sign bit; negative -> flip all bits.
__device__ __forceinline__ unsigned f2o(float f) {
    unsigned u = __float_as_uint(f);
    return (u & 0x80000000u) ? ~u : (u | 0x80000000u);
}
__device__ __forceinline__ float o2f(unsigned u) {
    u = (u & 0x80000000u) ? (u & 0x7FFFFFFFu) : ~u;
    return __uint_as_float(u);
}

// ---------------------------------------------------------------------------
// K0: zero out[], reset per-node max / denom.
// g_m init = 0u (the minimal encoded value). Nodes with no incoming edge are
// never decoded, and their out rows stay 0 (matches segment_sum of empty set).
// ---------------------------------------------------------------------------
__global__ void k_init(float4* __restrict__ out4) {
    int i = blockIdx.x * blockDim.x + threadIdx.x;
    if (i < (N_NODES * D) / 4) out4[i] = make_float4(0.f, 0.f, 0.f, 0.f);
    if (i < N_NODES) { g_m[i] = 0u; g_den[i] = 0.f; }
}

// ---------------------------------------------------------------------------
// K1: warp per edge. e = a_w . leaky_relu(h[src] + h[dst]); atomicMax into g_m.
// Each lane handles 2 consecutive floats (float2) -> coalesced 256B row reads.
// ---------------------------------------------------------------------------
__global__ void k_logits(const float* __restrict__ h,
                         const float* __restrict__ aw,
                         const int* __restrict__ src,
                         const int* __restrict__ dst) {
    int e    = (blockIdx.x * blockDim.x + threadIdx.x) >> 5;
    int lane = threadIdx.x & 31;
    if (e >= N_EDGES) return;
    int s = __ldg(&src[e]);
    int d = __ldg(&dst[e]);
    const float2* hs = (const float2*)(h + (size_t)s * D);
    const float2* hd = (const float2*)(h + (size_t)d * D);
    float2 a = __ldg(&hs[lane]);
    float2 b = __ldg(&hd[lane]);
    float2 w = __ldg(&((const float2*)aw)[lane]);
    float x = a.x + b.x; x = (x > 0.f) ? x : NEG_SLOPE * x;
    float y = a.y + b.y; y = (y > 0.f) ? y : NEG_SLOPE * y;
    float p = w.x * x + w.y * y;
    #pragma unroll
    for (int o = 16; o; o >>= 1) p += __shfl_xor_sync(0xffffffffu, p, o);
    if (lane == 0) {
        g_e[e] = p;
        atomicMax(&g_m[d], f2o(p));
    }
}

// ---------------------------------------------------------------------------
// K2: thread per edge. ex = exp(e - max[dst]); accumulate denominator.
// ---------------------------------------------------------------------------
__global__ void k_expsum(const int* __restrict__ dst) {
    int i = blockIdx.x * blockDim.x + threadIdx.x;
    if (i >= N_EDGES) return;
    int d = __ldg(&dst[i]);
    float m  = o2f(g_m[d]);
    float ex = __expf(g_e[i] - m);
    g_e[i] = ex;
    atomicAdd(&g_den[d], ex);
}

// ---------------------------------------------------------------------------
// K3: 16 lanes per edge (half-warp). alpha = ex/den[dst];
// out[dst] += alpha * h[src] via float4 vector atomics (RED.V4 on sm_90+).
// ---------------------------------------------------------------------------
__global__ void k_agg(const float* __restrict__ h,
                      const int* __restrict__ src,
                      const int* __restrict__ dst,
                      float* __restrict__ out) {
    int tid = blockIdx.x * blockDim.x + threadIdx.x;
    int e = tid >> 4;
    int l = tid & 15;
    if (e >= N_EDGES) return;
    int s = __ldg(&src[e]);
    int d = __ldg(&dst[e]);
    float alpha = g_e[e] / g_den[d];
    float4 v = __ldg(&((const float4*)(h + (size_t)s * D))[l]);
    v.x *= alpha; v.y *= alpha; v.z *= alpha; v.w *= alpha;
    atomicAdd((float4*)(out + (size_t)d * D + l * 4), v);
}

extern "C" void kernel_launch(void* const* d_in, const int* in_sizes, int n_in,
                              void* d_out, int out_size) {
    const float* h   = (const float*)d_in[0];
    const float* aw  = (const float*)d_in[1];
    const int*   src = (const int*)d_in[2];
    const int*   dst = (const int*)d_in[3];
    float* out = (float*)d_out;

    {
        int n = (N_NODES * D) / 4;  // 1.6M, covers N_NODES too
        k_init<<<(n + 255) / 256, 256>>>((float4*)out);
    }
    {
        long long t = (long long)N_EDGES * 32;
        k_logits<<<(int)((t + 255) / 256), 256>>>(h, aw, src, dst);
    }
    {
        k_expsum<<<(N_EDGES + 255) / 256, 256>>>(dst);
    }
    {
        long long t = (long long)N_EDGES * 16;
        k_agg<<<(int)((t + 255) / 256), 256>>>(h, src, dst, out);
    }
}

// round 2
// speedup vs baseline: 2.0005x; 2.0005x over previous
#include <cuda_runtime.h>
#include <cuda_bf16.h>
#include <math_constants.h>

#define N_NODES 100000
#define N_EDGES 1600000
#define D 64
#define NEG_SLOPE 0.1f

#define SCAN_BLK 1024
#define NCHUNK ((N_NODES + SCAN_BLK - 1) / SCAN_BLK)   // 98

// Scratch (__device__ globals; no allocation allowed)
__device__ int g_cnt[N_NODES];        // per-node in-degree
__device__ int g_rp[N_NODES + 1];     // CSR row pointers
__device__ int g_cur[N_NODES];        // scatter cursors
__device__ int g_blk[128];            // block sums for scan
__device__ int g_psrc[N_EDGES];       // CSR-ordered src node ids

// ---------------------------------------------------------------------------
// K0: zero degree counters
// ---------------------------------------------------------------------------
__global__ void k_zero() {
    int i = blockIdx.x * blockDim.x + threadIdx.x;
    if (i < N_NODES) g_cnt[i] = 0;
}

// ---------------------------------------------------------------------------
// K1: histogram of dst
// ---------------------------------------------------------------------------
__global__ void k_hist(const int* __restrict__ dst) {
    int e = blockIdx.x * blockDim.x + threadIdx.x;
    if (e < N_EDGES) atomicAdd(&g_cnt[dst[e]], 1);
}

// ---------------------------------------------------------------------------
// K2a: per-chunk exclusive scan (1024 elems/block), emit block totals
// ---------------------------------------------------------------------------
__global__ void k_scanA() {
    __shared__ int sh[SCAN_BLK];
    int t = threadIdx.x;
    int i = blockIdx.x * SCAN_BLK + t;
    int c = (i < N_NODES) ? g_cnt[i] : 0;
    sh[t] = c;
    __syncthreads();
    #pragma unroll
    for (int off = 1; off < SCAN_BLK; off <<= 1) {
        int v = (t >= off) ? sh[t - off] : 0;
        __syncthreads();
        if (t >= off) sh[t] += v;
        __syncthreads();
    }
    if (i < N_NODES) g_rp[i] = sh[t] - c;           // exclusive, chunk-local
    if (t == SCAN_BLK - 1) g_blk[blockIdx.x] = sh[t];
}

// ---------------------------------------------------------------------------
// K2b: scan the 98 block totals (single block)
// ---------------------------------------------------------------------------
__global__ void k_scanB() {
    __shared__ int sh[128];
    int t = threadIdx.x;
    int c = (t < NCHUNK) ? g_blk[t] : 0;
    sh[t] = c;
    __syncthreads();
    #pragma unroll
    for (int off = 1; off < 128; off <<= 1) {
        int v = (t >= off) ? sh[t - off] : 0;
        __syncthreads();
        if (t >= off) sh[t] += v;
        __syncthreads();
    }
    if (t < NCHUNK) g_blk[t] = sh[t] - c;           // exclusive
}

// ---------------------------------------------------------------------------
// K2c: add block offsets -> final row_ptr; init cursors
// ---------------------------------------------------------------------------
__global__ void k_scanC() {
    int i = blockIdx.x * blockDim.x + threadIdx.x;
    if (i < N_NODES) {
        int rp = g_rp[i] + g_blk[i / SCAN_BLK];
        g_rp[i] = rp;
        g_cur[i] = rp;
    }
    if (i == 0) g_rp[N_NODES] = N_EDGES;
}

// ---------------------------------------------------------------------------
// K3: scatter src ids into CSR order
// ---------------------------------------------------------------------------
__global__ void k_scatter(const int* __restrict__ src, const int* __restrict__ dst) {
    int e = blockIdx.x * blockDim.x + threadIdx.x;
    if (e < N_EDGES) {
        int p = atomicAdd(&g_cur[dst[e]], 1);
        g_psrc[p] = src[e];
    }
}

// ---------------------------------------------------------------------------
// K4: fused GAT node kernel. One warp per dst node. Online softmax:
//   per edge: gather h[src] (float2/lane), logit via butterfly reduce,
//   running (m, den, acc) update. Single gather pass, no atomics, one
//   row write per node.  h[src] load is software-pipelined one edge ahead.
// ---------------------------------------------------------------------------
__global__ void __launch_bounds__(256) k_node(const float* __restrict__ h,
                                              const float* __restrict__ aw,
                                              float* __restrict__ out) {
    int gw   = (blockIdx.x * blockDim.x + threadIdx.x) >> 5;
    int lane = threadIdx.x & 31;
    if (gw >= N_NODES) return;

    int beg = g_rp[gw];
    int end = g_rp[gw + 1];

    float2 aw2 = __ldg(&((const float2*)aw)[lane]);
    float2 hv  = __ldg(&((const float2*)(h + (size_t)gw * D))[lane]);

    float2 acc = make_float2(0.f, 0.f);
    float  m   = -CUDART_INF_F;
    float  den = 0.f;

    // pipeline: prefetch first edge's row
    float2 hs = make_float2(0.f, 0.f);
    if (beg < end) {
        int s0 = __ldg(&g_psrc[beg]);
        hs = __ldg(&((const float2*)(h + (size_t)s0 * D))[lane]);
    }

    for (int j = beg; j < end; j++) {
        float2 cur = hs;
        if (j + 1 < end) {                           // prefetch next edge
            int sn = __ldg(&g_psrc[j + 1]);
            hs = __ldg(&((const float2*)(h + (size_t)sn * D))[lane]);
        }
        float x = hv.x + cur.x; x = (x > 0.f) ? x : NEG_SLOPE * x;
        float y = hv.y + cur.y; y = (y > 0.f) ? y : NEG_SLOPE * y;
        float p = aw2.x * x + aw2.y * y;
        #pragma unroll
        for (int o = 16; o; o >>= 1) p += __shfl_xor_sync(0xffffffffu, p, o);

        if (p <= m) {                                // warp-uniform branch
            float w = __expf(p - m);
            den += w;
            acc.x += w * cur.x;
            acc.y += w * cur.y;
        } else {
            float c = __expf(m - p);                 // exp(-inf)=0 on first edge
            den = den * c + 1.f;
            acc.x = acc.x * c + cur.x;
            acc.y = acc.y * c + cur.y;
            m = p;
        }
    }

    float inv = (den > 0.f) ? (1.f / den) : 0.f;     // deg-0 nodes -> zeros
    ((float2*)(out + (size_t)gw * D))[lane] = make_float2(acc.x * inv, acc.y * inv);
}

extern "C" void kernel_launch(void* const* d_in, const int* in_sizes, int n_in,
                              void* d_out, int out_size) {
    const float* h   = (const float*)d_in[0];
    const float* aw  = (const float*)d_in[1];
    const int*   src = (const int*)d_in[2];
    const int*   dst = (const int*)d_in[3];
    float* out = (float*)d_out;

    k_zero<<<(N_NODES + 255) / 256, 256>>>();
    k_hist<<<(N_EDGES + 255) / 256, 256>>>(dst);
    k_scanA<<<NCHUNK, SCAN_BLK>>>();
    k_scanB<<<1, 128>>>();
    k_scanC<<<(N_NODES + 255) / 256, 256>>>();
    k_scatter<<<(N_EDGES + 255) / 256, 256>>>(src, dst);

    long long t = (long long)N_NODES * 32;
    k_node<<<(int)((t + 255) / 256), 256>>>(h, aw, out);
}